// round 2
// baseline (speedup 1.0000x reference)
#include <cuda_runtime.h>

#define NN 128
#define TT 2048
#define DD 88
#define D4 (DD / 4)   // 22 float4 per row

// Scratch (no device allocation allowed -> __device__ globals)
__device__ float g_tprow[NN * TT];
__device__ float g_fpfn [NN * TT];
__device__ float g_acc  [NN];

// ---------------------------------------------------------------------------
// k1: one warp per (n,t) row. Lanes 0..21 each load one float4 from output
// and target (row base is 352B = 16B-aligned), compute tp and fp+fn partials,
// warp-reduce, lane 0 writes per-row scratch.
// ---------------------------------------------------------------------------
__global__ void __launch_bounds__(256) k1_rowstats(
    const float4* __restrict__ outp, const float4* __restrict__ tgtp)
{
    const int n    = blockIdx.y;
    const int t    = blockIdx.x * blockDim.y + threadIdx.y;
    const int lane = threadIdx.x;

    const size_t row  = (size_t)n * TT + t;
    const size_t base = row * D4;

    float tp = 0.f, fpfn = 0.f;
    if (lane < D4) {
        float4 o = outp[base + lane];
        float4 g = tgtp[base + lane];
        float p;
        p = (o.x > 0.f) ? 1.f : 0.f; tp += p * g.x; fpfn += p + g.x - 2.f * p * g.x;
        p = (o.y > 0.f) ? 1.f : 0.f; tp += p * g.y; fpfn += p + g.y - 2.f * p * g.y;
        p = (o.z > 0.f) ? 1.f : 0.f; tp += p * g.z; fpfn += p + g.z - 2.f * p * g.z;
        p = (o.w > 0.f) ? 1.f : 0.f; tp += p * g.w; fpfn += p + g.w - 2.f * p * g.w;
    }
    #pragma unroll
    for (int off = 16; off; off >>= 1) {
        tp   += __shfl_down_sync(0xffffffffu, tp,   off);
        fpfn += __shfl_down_sync(0xffffffffu, fpfn, off);
    }
    if (lane == 0) {
        g_tprow[row] = tp;
        g_fpfn [row] = fpfn;
    }
}

// ---------------------------------------------------------------------------
// k2: one block per sequence n. Reduce tp over t, reduce mask -> T_i, then
// sum ratios for valid timesteps, write acc[n].
// ---------------------------------------------------------------------------
__global__ void __launch_bounds__(256) k2_perseq(const int* __restrict__ mask)
{
    const int n   = blockIdx.x;
    const int tid = threadIdx.x;
    __shared__ float sf[256];
    __shared__ int   si[256];

    // total true positives for this sequence
    float tp = 0.f;
    for (int t = tid; t < TT; t += 256) tp += g_tprow[(size_t)n * TT + t];
    sf[tid] = tp; __syncthreads();
    #pragma unroll
    for (int s = 128; s; s >>= 1) { if (tid < s) sf[tid] += sf[tid + s]; __syncthreads(); }
    const float tp_tot = sf[0];
    __syncthreads();

    // T_i = number of valid timesteps
    int ti = 0;
    for (int t = tid; t < TT; t += 256) ti += mask[(size_t)n * TT + t];
    si[tid] = ti; __syncthreads();
    #pragma unroll
    for (int s = 128; s; s >>= 1) { if (tid < s) si[tid] += si[tid + s]; __syncthreads(); }
    const int Ti = si[0];
    __syncthreads();

    // sum of ratios over valid timesteps (left-aligned validity: t < Ti)
    float acc = 0.f;
    for (int t = tid; t < TT; t += 256) {
        if (t < Ti) {
            const float d = g_fpfn[(size_t)n * TT + t];
            acc += tp_tot / (tp_tot + d);
        }
    }
    sf[tid] = acc; __syncthreads();
    #pragma unroll
    for (int s = 128; s; s >>= 1) { if (tid < s) sf[tid] += sf[tid + s]; __syncthreads(); }

    if (tid == 0) g_acc[n] = sf[0] / (float)Ti;
}

// ---------------------------------------------------------------------------
// k3: deterministic final reduction of 128 per-sequence accuracies.
// ---------------------------------------------------------------------------
__global__ void __launch_bounds__(128) k3_final(float* __restrict__ out)
{
    __shared__ float sf[128];
    sf[threadIdx.x] = g_acc[threadIdx.x];
    __syncthreads();
    #pragma unroll
    for (int s = 64; s; s >>= 1) {
        if (threadIdx.x < s) sf[threadIdx.x] += sf[threadIdx.x + s];
        __syncthreads();
    }
    if (threadIdx.x == 0) out[0] = sf[0];
}

extern "C" void kernel_launch(void* const* d_in, const int* in_sizes, int n_in,
                              void* d_out, int out_size)
{
    const float4* outp = (const float4*)d_in[0];
    const float4* tgtp = (const float4*)d_in[1];
    const int*    mask = (const int*)  d_in[2];
    float*        out  = (float*)d_out;

    dim3 grid1(TT / 8, NN);      // 256 x 128 blocks
    dim3 blk1(32, 8);            // one warp per row, 8 rows per block
    k1_rowstats<<<grid1, blk1>>>(outp, tgtp);
    k2_perseq<<<NN, 256>>>(mask);
    k3_final<<<1, 128>>>(out);
}

// round 3
// speedup vs baseline: 1.3647x; 1.3647x over previous
#include <cuda_runtime.h>

#define NN 128
#define TT 2048
#define DD 88
#define D4 22            // float4 per row
#define THREADS 1024
#define WARPS 32
#define ROWS_PER_WARP 4
#define ROWS_PER_ITER (WARPS * ROWS_PER_WARP)   // 128
#define NITER (TT / ROWS_PER_ITER)              // 16

__device__ float        g_acc[NN];
__device__ unsigned int g_count = 0;

__global__ void __launch_bounds__(THREADS) fused_accuracy(
    const float4* __restrict__ outp,
    const float4* __restrict__ tgtp,
    const int*    __restrict__ mask,
    float*        __restrict__ out)
{
    const int n    = blockIdx.x;
    const int tid  = threadIdx.x;
    const int warp = tid >> 5;
    const int lane = tid & 31;

    __shared__ float s_fpfn[TT];     // per-timestep fp+fn counts
    __shared__ int   s_redi[WARPS];
    __shared__ float s_redf[WARPS];

    const size_t nbase = (size_t)n * TT * D4;

    int tp_i = 0;   // per-thread true-positive count (integer-exact)

    #pragma unroll 1
    for (int iter = 0; iter < NITER; iter++) {
        const int t0 = iter * ROWS_PER_ITER + warp * ROWS_PER_WARP;
        const size_t base = nbase + (size_t)t0 * D4 + lane;
        const bool act = (lane < D4);

        float4 o0, o1, o2, o3, g0, g1, g2, g3;
        if (act) {
            o0 = outp[base];
            o1 = outp[base + D4];
            o2 = outp[base + 2 * D4];
            o3 = outp[base + 3 * D4];
            g0 = tgtp[base];
            g1 = tgtp[base + D4];
            g2 = tgtp[base + 2 * D4];
            g3 = tgtp[base + 3 * D4];
        }

        // fpfn counts for 4 rows packed into one int (8 bits each, max 88 per row)
        int fp = 0;
        if (act) {
            int f0 = 0, f1 = 0, f2 = 0, f3 = 0;
            #define ELEM(ov, gv, fv) {                      \
                const bool p = ((ov) > 0.f);                \
                const bool q = ((gv) != 0.f);               \
                tp_i += (p && q) ? 1 : 0;                   \
                fv   += (p != q) ? 1 : 0; }
            ELEM(o0.x, g0.x, f0) ELEM(o0.y, g0.y, f0) ELEM(o0.z, g0.z, f0) ELEM(o0.w, g0.w, f0)
            ELEM(o1.x, g1.x, f1) ELEM(o1.y, g1.y, f1) ELEM(o1.z, g1.z, f1) ELEM(o1.w, g1.w, f1)
            ELEM(o2.x, g2.x, f2) ELEM(o2.y, g2.y, f2) ELEM(o2.z, g2.z, f2) ELEM(o2.w, g2.w, f2)
            ELEM(o3.x, g3.x, f3) ELEM(o3.y, g3.y, f3) ELEM(o3.z, g3.z, f3) ELEM(o3.w, g3.w, f3)
            #undef ELEM
            fp = f0 | (f1 << 8) | (f2 << 16) | (f3 << 24);
        }

        // one 5-step butterfly reduces all 4 rows at once (byte-packed, no overflow)
        #pragma unroll
        for (int off = 16; off; off >>= 1)
            fp += __shfl_down_sync(0xffffffffu, fp, off);

        if (lane == 0) {
            s_fpfn[t0 + 0] = (float)( fp        & 0xff);
            s_fpfn[t0 + 1] = (float)((fp >> 8)  & 0xff);
            s_fpfn[t0 + 2] = (float)((fp >> 16) & 0xff);
            s_fpfn[t0 + 3] = (float)((fp >> 24) & 0xff);
        }
    }

    // ---- block reduce: pack tp (<=180224, 18 bits) and mask count (<=2048) ----
    int ti = mask[(size_t)n * TT + tid] + mask[(size_t)n * TT + tid + THREADS];
    int pk = tp_i + (ti << 18);
    #pragma unroll
    for (int off = 16; off; off >>= 1)
        pk += __shfl_down_sync(0xffffffffu, pk, off);
    if (lane == 0) s_redi[warp] = pk;
    __syncthreads();
    if (warp == 0) {
        int v = s_redi[lane];
        #pragma unroll
        for (int off = 16; off; off >>= 1)
            v += __shfl_down_sync(0xffffffffu, v, off);
        if (lane == 0) s_redi[0] = v;
    }
    __syncthreads();

    const int   Ti     = s_redi[0] >> 18;
    const float tp_tot = (float)(s_redi[0] & 0x3ffff);

    // ---- ratio sum over valid timesteps ----
    float acc = 0.f;
    {
        int t = tid;
        if (t < Ti)            acc += tp_tot / (tp_tot + s_fpfn[t]);
        t = tid + THREADS;
        if (t < Ti)            acc += tp_tot / (tp_tot + s_fpfn[t]);
    }
    #pragma unroll
    for (int off = 16; off; off >>= 1)
        acc += __shfl_down_sync(0xffffffffu, acc, off);
    if (lane == 0) s_redf[warp] = acc;
    __syncthreads();
    if (warp == 0) {
        float v = s_redf[lane];
        #pragma unroll
        for (int off = 16; off; off >>= 1)
            v += __shfl_down_sync(0xffffffffu, v, off);
        if (lane == 0) g_acc[n] = v / (float)Ti;
    }

    // ---- last-block-done final reduction (deterministic fixed-order sum) ----
    __shared__ int s_isLast;
    if (tid == 0) {
        __threadfence();
        unsigned int old = atomicAdd(&g_count, 1u);
        s_isLast = (old == (unsigned)(gridDim.x - 1)) ? 1 : 0;
    }
    __syncthreads();
    if (s_isLast && warp == 0) {
        __threadfence();
        float v = g_acc[lane] + g_acc[lane + 32] + g_acc[lane + 64] + g_acc[lane + 96];
        #pragma unroll
        for (int off = 16; off; off >>= 1)
            v += __shfl_down_sync(0xffffffffu, v, off);
        if (lane == 0) {
            out[0]  = v;
            g_count = 0;   // reset for next graph replay
        }
    }
}

extern "C" void kernel_launch(void* const* d_in, const int* in_sizes, int n_in,
                              void* d_out, int out_size)
{
    const float4* outp = (const float4*)d_in[0];
    const float4* tgtp = (const float4*)d_in[1];
    const int*    mask = (const int*)  d_in[2];
    float*        out  = (float*)d_out;

    fused_accuracy<<<NN, THREADS>>>(outp, tgtp, mask, out);
}